// round 3
// baseline (speedup 1.0000x reference)
#include <cuda_runtime.h>

// Shapes fixed by the problem: N=8192, D=64.
#define N_ROWS 8192
#define D_DIM  64

#define COLS4          (N_ROWS / 4)     // 2048 float4 per row
#define THREADS        256
#define STRIPS         (COLS4 / THREADS) // 8 column strips of 1024 floats
#define ROWS_PER_BLOCK 32
#define ROW_UNROLL     4

// Scratch for GEMV results (no cudaMalloc allowed).
__device__ float g_s1[N_ROWS];
__device__ float g_s2[N_ROWS];

// Kernel 1: s1 = Wh @ a[:64], s2 = Wh @ a[64:128].
// One warp per row; each lane owns a float2 (64 elems / 32 lanes).
__global__ void gemv_kernel(const float* __restrict__ Wh,
                            const float* __restrict__ a) {
    const int warps_per_block = blockDim.x >> 5;
    const int row  = blockIdx.x * warps_per_block + (threadIdx.x >> 5);
    const int lane = threadIdx.x & 31;
    if (row >= N_ROWS) return;

    const float2 w  = reinterpret_cast<const float2*>(Wh + (size_t)row * D_DIM)[lane];
    const float2 a1 = reinterpret_cast<const float2*>(a)[lane];
    const float2 a2 = reinterpret_cast<const float2*>(a + D_DIM)[lane];

    float s1 = w.x * a1.x + w.y * a1.y;
    float s2 = w.x * a2.x + w.y * a2.y;

    #pragma unroll
    for (int off = 16; off > 0; off >>= 1) {
        s1 += __shfl_xor_sync(0xFFFFFFFFu, s1, off);
        s2 += __shfl_xor_sync(0xFFFFFFFFu, s2, off);
    }
    if (lane == 0) {
        g_s1[row] = s1;
        g_s2[row] = s2;
    }
}

__device__ __forceinline__ float leaky(float e) {
    // e >= 0 ? e : 0.2*e  ==  max(e, 0.2*e) for all e
    return fmaxf(e, 0.2f * e);
}

__device__ __forceinline__ float4 row_vals(float s1, float4 s2) {
    float4 e;
    e.x = leaky(s1 + s2.x);
    e.y = leaky(s1 + s2.y);
    e.z = leaky(s1 + s2.z);
    e.w = leaky(s1 + s2.w);
    return e;
}

// Kernel 2: out[i][j] = leaky(s1[i] + s2[j]).
// Each block owns a 1024-float column strip; s2 chunk lives in a register.
// Loop over 32 rows, unrolled x4 for independent in-flight stores.
__global__ __launch_bounds__(THREADS) void outer_kernel(float4* __restrict__ out) {
    const int c4   = blockIdx.x * THREADS + threadIdx.x;   // 0..2047
    const int row0 = blockIdx.y * ROWS_PER_BLOCK;

    const float4 s2 = reinterpret_cast<const float4*>(g_s2)[c4];
    float4* dst = out + (size_t)row0 * COLS4 + c4;

    #pragma unroll 2
    for (int r = 0; r < ROWS_PER_BLOCK; r += ROW_UNROLL) {
        float a0 = g_s1[row0 + r + 0];
        float a1 = g_s1[row0 + r + 1];
        float a2 = g_s1[row0 + r + 2];
        float a3 = g_s1[row0 + r + 3];

        float4 e0 = row_vals(a0, s2);
        float4 e1 = row_vals(a1, s2);
        float4 e2 = row_vals(a2, s2);
        float4 e3 = row_vals(a3, s2);

        __stcs(dst + 0 * (size_t)COLS4, e0);
        __stcs(dst + 1 * (size_t)COLS4, e1);
        __stcs(dst + 2 * (size_t)COLS4, e2);
        __stcs(dst + 3 * (size_t)COLS4, e3);
        dst += (size_t)ROW_UNROLL * COLS4;
    }
}

extern "C" void kernel_launch(void* const* d_in, const int* in_sizes, int n_in,
                              void* d_out, int out_size) {
    const float* Wh = (const float*)d_in[0];
    const float* a  = (const float*)d_in[1];
    float4* out = (float4*)d_out;

    // Kernel 1: 8192 warps -> 8 warps/block, 1024 blocks
    gemv_kernel<<<N_ROWS / 8, 256>>>(Wh, a);

    // Kernel 2: 8 column strips x 256 row-chunks = 2048 blocks
    dim3 grid(STRIPS, N_ROWS / ROWS_PER_BLOCK);
    outer_kernel<<<grid, THREADS>>>(out);
}